// round 16
// baseline (speedup 1.0000x reference)
#include <cuda_runtime.h>
#include <cuda_fp16.h>

#define W 960
#define H 512
#define C 16
#define HW (H * W)
#define WPAIR 480

// dual parity-aligned pair-packed fp16 images:
// g_h4e: pair j covers pixels (2j, 2j+1); g_h4o: pair j covers (2j+1, 2j+2)
__device__ uint4 g_h4e[H * WPAIR * 4];
__device__ uint4 g_h4o[H * WPAIR * 4];

__device__ __forceinline__ unsigned h2pack(float a, float b) {
    __half2 h = __floats2half2_rn(a, b);
    return *reinterpret_cast<unsigned*>(&h);
}
__device__ __forceinline__ __half2 u2h(unsigned v) {
    return *reinterpret_cast<__half2*>(&v);
}
__device__ __forceinline__ unsigned h2u(__half2 h) {
    return *reinterpret_cast<unsigned*>(&h);
}

// ---------------- transpose+pack: warp-shuffle, no smem, both copies ----------------
__global__ __launch_bounds__(256) void transpose_kernel(const float* __restrict__ img)
{
    const int gw   = blockIdx.x * 8 + (threadIdx.x >> 5);
    const int lane = threadIdx.x & 31;
    const int row  = gw / 30;
    const int b    = (gw % 30) * 32;

#pragma unroll
    for (int pass = 0; pass < 2; pass++) {
        const int px = b + pass + lane;
        const bool valid = (px < W);
        const float* src = img + row * W + px;

        float v[16];
#pragma unroll
        for (int c = 0; c < 16; c++)
            v[c] = valid ? __ldg(src + c * HW) : 0.f;

        unsigned wd[8];
#pragma unroll
        for (int cg = 0; cg < 4; cg++) {
            wd[cg*2+0] = h2pack(v[cg*4+0], v[cg*4+1]);
            wd[cg*2+1] = h2pack(v[cg*4+2], v[cg*4+3]);
        }
        unsigned od[8];
#pragma unroll
        for (int t = 0; t < 8; t++)
            od[t] = __shfl_down_sync(0xffffffffu, wd[t], 1);

        if ((lane & 1) == 0) {
            const int pairj = (b >> 1) + (lane >> 1);
            uint4* dst = pass ? g_h4o : g_h4e;
#pragma unroll
            for (int cg = 0; cg < 4; cg++)
                dst[(row * WPAIR + pairj) * 4 + cg] =
                    make_uint4(wd[cg*2], wd[cg*2+1], od[cg*2], od[cg*2+1]);
        }
    }
}

// ---------------- scatter-patch reconstruct (barrier-free stores) ----------------
#define TILE 16
#define NCELL (TILE * TILE)
#define HALO 18
#define NUNIT (HALO * HALO)   /* 324 */
#define NUPAD 328
#define NWAVE 3
#define THREADS 512

__global__ __launch_bounds__(THREADS, 4) void recon_scatter(
    const float* __restrict__ offx,
    const float* __restrict__ offy,
    float* __restrict__ out)
{
    // params: 3 uint4 per unit (48B stride: bank-quads 3k&7 distinct -> conflict-free)
    __shared__ uint4 upq[NUPAD * 3];        // 15.7 KB
    __shared__ unsigned upb[NUPAD];         // 1.3 KB (base|parity, broadcast per unit)
    __shared__ uint2 comb[3][NCELL * 4];    // 24 KB
    __shared__ uint2 lft[NCELL * 4];        // 8 KB

    const int tid = threadIdx.x;
    const int h0 = blockIdx.y * TILE;
    const int w0 = blockIdx.x * TILE;

    for (int i = tid; i < NCELL * 4; i += THREADS) lft[i] = make_uint2(0u, 0u);

    // ---------- phase A: per-unit params ----------
    if (tid < NUPAD) {
        const int u = tid;
        const int ur = u / HALO, uc = u % HALO;
        const int hh = h0 - 1 + ur, ww = w0 - 1 + uc;
        unsigned ub[13];
#pragma unroll
        for (int k = 0; k < 13; k++) ub[k] = 0u;

        if (u < NUNIT && hh >= 0 && hh < H && ww >= 0 && ww < W) {
            const float sx = __ldg(offx + hh * W + ww);
            const float sy = __ldg(offy + hh * W + ww);

            // ---- x: 4-wide unaligned window ----
            int x0a[3]; float fxa[3], ma[3]; int pmin = W;
#pragma unroll
            for (int dj = 0; dj < 3; dj++) {
                const int wt = ww + 1 - dj;
                float m = (wt >= 0 && wt < W) ? 1.f : 0.f;
                if (ww == 1     && wt == 0    ) m += 1.f;
                if (ww == W - 2 && wt == W - 1) m += 1.f;
                float cx  = fminf(fmaxf((float)wt - sx, 0.f), (float)(W - 1));
                float ix  = cx * ((float)(W - 1) / (float)W);
                float x0f = floorf(ix);
                x0a[dj] = (int)x0f; fxa[dj] = ix - x0f; ma[dj] = m;
                if (m != 0.f) pmin = min(pmin, x0a[dj]);
            }
            const int px = min(max(pmin, 0), W - 4);
            const unsigned parity = (unsigned)(px & 1);
#pragma unroll
            for (int dj = 0; dj < 3; dj++) {
                const int l = min(max(x0a[dj] - px, 0), 2);
                float v[4];
#pragma unroll
                for (int c = 0; c < 4; c++)
                    v[c] = ma[dj] * ((c == l) ? (1.f - fxa[dj])
                                   : ((c == l + 1) ? fxa[dj] : 0.f));
                ub[dj * 2 + 0] = h2pack(v[0], v[1]);
                ub[dj * 2 + 1] = h2pack(v[2], v[3]);
            }

            // ---- y ----
            int y0a[3]; float fya[3], mya[3]; int qmin = H;
#pragma unroll
            for (int di = 0; di < 3; di++) {
                const int ht = hh + 1 - di;
                float m = (ht >= 0 && ht < H) ? 1.f : 0.f;
                if (hh == 1     && ht == 0    ) m += 1.f;
                if (hh == H - 2 && ht == H - 1) m += 1.f;
                float cy  = fminf(fmaxf((float)ht - sy, 0.f), (float)(H - 1));
                float iy  = cy * ((float)(H - 1) / (float)H);
                float y0f = floorf(iy);
                y0a[di] = (int)y0f; fya[di] = iy - y0f; mya[di] = m;
                if (m != 0.f) qmin = min(qmin, y0a[di]);
            }
            const int py = min(qmin, H - 4);
#pragma unroll
            for (int di = 0; di < 3; di++) {
                const int l = min(max(y0a[di] - py, 0), 2);
                float g[4];
#pragma unroll
                for (int r = 0; r < 4; r++)
                    g[r] = mya[di] * ((r == l) ? (1.f - fya[di])
                                    : ((r == l + 1) ? fya[di] : 0.f));
                ub[6 + di] = h2pack(g[0], g[1]);
                ub[9 + di] = h2pack(g[2], g[3]);
            }
            upb[u] = (unsigned)((py * WPAIR + (px >> 1)) * 4) | (parity << 31);
        } else {
            upb[u] = 0u;
        }
        upq[u * 3 + 0] = make_uint4(ub[0], ub[1], ub[2],  ub[3]);
        upq[u * 3 + 1] = make_uint4(ub[4], ub[5], ub[6],  ub[7]);
        upq[u * 3 + 2] = make_uint4(ub[8], ub[9], ub[10], ub[11]);
    }
    __syncthreads();

    // ---------- phase B: 3 waves, NO barriers ----------
    const int cg = tid & 3;
    const int k  = (tid & 31) >> 2;

    for (int wave = 0; wave < NWAVE; wave++) {
        const bool wactive = (wave * 128 + ((tid >> 5) << 3)) < NUNIT;
        if (!wactive) continue;

        const int u = wave * 128 + (tid >> 2);

        const uint4 q0 = upq[u * 3 + 0];
        const uint4 q1 = upq[u * 3 + 1];
        const uint4 q2 = upq[u * 3 + 2];
        const unsigned bw = upb[u];

        const unsigned wxlo[3] = {q0.x, q0.z, q1.x};
        const unsigned wxhi[3] = {q0.y, q0.w, q1.y};
        const unsigned wy01v[3] = {q1.z, q1.w, q2.x};
        const unsigned wy23v[3] = {q2.y, q2.z, q2.w};
        const int base = (int)(bw & 0x7fffffffu) + cg;
        const uint4* __restrict__ imgp = (bw >> 31) ? g_h4o : g_h4e;
        const int ur = u / HALO, uc = u % HALO;

        const __half2 hz = __float2half2_rn(0.f);
        __half2 o01[9], o23[9];
#pragma unroll
        for (int p = 0; p < 9; p++) { o01[p] = hz; o23[p] = hz; }

#pragma unroll
        for (int r = 0; r < 4; r++) {
            const int qb = base + r * (WPAIR * 4);
            const uint4 P0 = __ldg(imgp + qb);
            const uint4 P1 = __ldg(imgp + qb + 4);

            const __half2 C01_0 = u2h(P0.x);
            const __half2 C01_1 = u2h(P0.z);
            const __half2 C01_2 = u2h(P1.x);
            const __half2 C01_3 = u2h(P1.z);
            const __half2 C23_0 = u2h(P0.y);
            const __half2 C23_1 = u2h(P0.w);
            const __half2 C23_2 = u2h(P1.y);
            const __half2 C23_3 = u2h(P1.w);

#pragma unroll
            for (int dj = 0; dj < 3; dj++) {
                const __half2 w0v = __low2half2 (u2h(wxlo[dj]));
                const __half2 w1v = __high2half2(u2h(wxlo[dj]));
                const __half2 w2v = __low2half2 (u2h(wxhi[dj]));
                const __half2 w3v = __high2half2(u2h(wxhi[dj]));

                __half2 t01 = __hmul2(C01_0, w0v);
                __half2 t23 = __hmul2(C23_0, w0v);
                t01 = __hfma2(C01_1, w1v, t01);
                t23 = __hfma2(C23_1, w1v, t23);
                t01 = __hfma2(C01_2, w2v, t01);
                t23 = __hfma2(C23_2, w2v, t23);
                t01 = __hfma2(C01_3, w3v, t01);
                t23 = __hfma2(C23_3, w3v, t23);
#pragma unroll
                for (int di = 0; di < 3; di++) {
                    const unsigned wsel = (r < 2) ? wy01v[di] : wy23v[di];
                    const __half2 g = ((r & 1) == 0) ? __low2half2(u2h(wsel))
                                                     : __high2half2(u2h(wsel));
                    o01[di*3+dj] = __hfma2(t01, g, o01[di*3+dj]);
                    o23[di*3+dj] = __hfma2(t23, g, o23[di*3+dj]);
                }
            }
        }

        // ---- comb stores (store-once; STS.64) ----
#pragma unroll
        for (int di = 0; di < 3; di++) {
            const int row = ur - di;
            const unsigned a1 = __shfl_down_sync(0xffffffffu, h2u(o01[di*3+1]), 4);
            const unsigned b1 = __shfl_down_sync(0xffffffffu, h2u(o23[di*3+1]), 4);
            const unsigned a2 = __shfl_down_sync(0xffffffffu, h2u(o01[di*3+2]), 8);
            const unsigned b2 = __shfl_down_sync(0xffffffffu, h2u(o23[di*3+2]), 8);
            __half2 c01 = o01[di*3+0];
            __half2 c23 = o23[di*3+0];
            if (k <= 6) { c01 = __hadd2(c01, u2h(a1)); c23 = __hadd2(c23, u2h(b1)); }
            if (k <= 5) { c01 = __hadd2(c01, u2h(a2)); c23 = __hadd2(c23, u2h(b2)); }
            if ((unsigned)row < (unsigned)TILE && (unsigned)uc < (unsigned)TILE) {
                comb[di][(row * TILE + uc) * 4 + cg] = make_uint2(h2u(c01), h2u(c23));
            }
        }

        // ---- leftovers (k==0 lanes; store-once, proven distinct) ----
#pragma unroll
        for (int di = 0; di < 3; di++) {
            const int row = ur - di;
            const unsigned la = __shfl_down_sync(0xffffffffu, h2u(o01[di*3+2]), 4);
            const unsigned lb = __shfl_down_sync(0xffffffffu, h2u(o23[di*3+2]), 4);
            if (k == 0) {
                if ((unsigned)row < (unsigned)TILE &&
                    (unsigned)(uc - 1) < (unsigned)TILE) {
                    lft[(row * TILE + (uc - 1)) * 4 + cg] =
                        make_uint2(h2u(__hadd2(o01[di*3+1], u2h(la))),
                                   h2u(__hadd2(o23[di*3+1], u2h(lb))));
                }
                if ((unsigned)row < (unsigned)TILE &&
                    (unsigned)(uc - 2) < (unsigned)TILE) {
                    lft[(row * TILE + (uc - 2)) * 4 + cg] =
                        make_uint2(h2u(o01[di*3+2]), h2u(o23[di*3+2]));
                }
            }
        }
    }
    __syncthreads();

    // ---------- writeback ----------
    const float inv9 = 1.0f / 9.0f;
#pragma unroll
    for (int pass = 0; pass < 2; pass++) {
        const int a = pass * THREADS + tid;
        const int cell = a >> 2;
        const int acg  = a & 3;
        const int gidx = (h0 + (cell >> 4)) * W + (w0 + (cell & 15));

        const uint2 L = lft[a];
        float2 s01 = __half22float2(u2h(L.x));
        float2 s23 = __half22float2(u2h(L.y));
#pragma unroll
        for (int di = 0; di < 3; di++) {
            const uint2 Cc = comb[di][a];
            const float2 c0 = __half22float2(u2h(Cc.x));
            const float2 c2 = __half22float2(u2h(Cc.y));
            s01.x += c0.x; s01.y += c0.y;
            s23.x += c2.x; s23.y += c2.y;
        }
        out[(4*acg + 0) * HW + gidx] = s01.x * inv9;
        out[(4*acg + 1) * HW + gidx] = s01.y * inv9;
        out[(4*acg + 2) * HW + gidx] = s23.x * inv9;
        out[(4*acg + 3) * HW + gidx] = s23.y * inv9;
    }
}

extern "C" void kernel_launch(void* const* d_in, const int* in_sizes, int n_in,
                              void* d_out, int out_size)
{
    const float* img  = (const float*)d_in[0];
    const float* offx = (const float*)d_in[1];
    const float* offy = (const float*)d_in[2];
    float* out = (float*)d_out;

    transpose_kernel<<<1920, 256>>>(img);

    dim3 grid(W / TILE, H / TILE);
    recon_scatter<<<grid, THREADS>>>(offx, offy, out);
}

// round 17
// speedup vs baseline: 4.2119x; 4.2119x over previous
#include <cuda_runtime.h>
#include <cuda_fp16.h>

#define W 960
#define H 512
#define C 16
#define HW (H * W)
#define WPAIR 480

// dual parity-aligned pair-packed fp16 images:
// g_h4e: pair j covers pixels (2j, 2j+1); g_h4o: pair j covers (2j+1, 2j+2)
__device__ uint4 g_h4e[H * WPAIR * 4];
__device__ uint4 g_h4o[H * WPAIR * 4];

__device__ __forceinline__ unsigned h2pack(float a, float b) {
    __half2 h = __floats2half2_rn(a, b);
    return *reinterpret_cast<unsigned*>(&h);
}
__device__ __forceinline__ __half2 u2h(unsigned v) {
    return *reinterpret_cast<__half2*>(&v);
}
__device__ __forceinline__ unsigned h2u(__half2 h) {
    return *reinterpret_cast<unsigned*>(&h);
}

// ---------------- transpose+pack: single-pass, both copies ----------------
// lane l holds pixel b+l. Even lanes emit even-copy pair (px,px+1);
// odd lanes emit odd-copy pair (px,px+1). Partner via shfl_down(1);
// lane 31 loads its partner directly (zero past row end).
__global__ __launch_bounds__(256) void transpose_kernel(const float* __restrict__ img)
{
    const int gw   = blockIdx.x * 8 + (threadIdx.x >> 5);
    const int lane = threadIdx.x & 31;
    const int row  = gw / 30;
    const int b    = (gw % 30) * 32;
    const int px   = b + lane;

    const float* src = img + row * W + px;
    float v[16];
#pragma unroll
    for (int c = 0; c < 16; c++)
        v[c] = __ldg(src + c * HW);

    unsigned wd[8];
#pragma unroll
    for (int cg = 0; cg < 4; cg++) {
        wd[cg*2+0] = h2pack(v[cg*4+0], v[cg*4+1]);
        wd[cg*2+1] = h2pack(v[cg*4+2], v[cg*4+3]);
    }

    unsigned od[8];
#pragma unroll
    for (int t = 0; t < 8; t++)
        od[t] = __shfl_down_sync(0xffffffffu, wd[t], 1);

    if (lane == 31) {
        const bool pv = (px + 1 < W);
        float nv[16];
#pragma unroll
        for (int c = 0; c < 16; c++)
            nv[c] = pv ? __ldg(src + 1 + c * HW) : 0.f;
#pragma unroll
        for (int cg = 0; cg < 4; cg++) {
            od[cg*2+0] = h2pack(nv[cg*4+0], nv[cg*4+1]);
            od[cg*2+1] = h2pack(nv[cg*4+2], nv[cg*4+3]);
        }
    }

    // even lane: even-copy pair j = px/2 ; odd lane: odd-copy pair j = (px-1)/2
    const int j = px >> 1;
    uint4* dst = (lane & 1) ? g_h4o : g_h4e;
#pragma unroll
    for (int cg = 0; cg < 4; cg++)
        dst[(row * WPAIR + j) * 4 + cg] =
            make_uint4(wd[cg*2], wd[cg*2+1], od[cg*2], od[cg*2+1]);
}

// ---------------- scatter-patch reconstruct (barrier-free stores) ----------------
#define TILE 16
#define NCELL (TILE * TILE)
#define HALO 18
#define NUNIT (HALO * HALO)   /* 324 */
#define NUPAD 328
#define NWAVE 3
#define THREADS 512

__global__ __launch_bounds__(THREADS, 2) void recon_scatter(
    const float* __restrict__ offx,
    const float* __restrict__ offy,
    float* __restrict__ out)
{
    // params: 3 uint4 per unit (48B stride, conflict-free) + broadcast base word
    __shared__ uint4 upq[NUPAD * 3];
    __shared__ unsigned upb[NUPAD];
    __shared__ uint2 comb[3][NCELL * 4];
    __shared__ uint2 lft[NCELL * 4];

    const int tid = threadIdx.x;
    const int h0 = blockIdx.y * TILE;
    const int w0 = blockIdx.x * TILE;

    for (int i = tid; i < NCELL * 4; i += THREADS) lft[i] = make_uint2(0u, 0u);

    // ---------- phase A: per-unit params ----------
    if (tid < NUPAD) {
        const int u = tid;
        const int ur = u / HALO, uc = u % HALO;
        const int hh = h0 - 1 + ur, ww = w0 - 1 + uc;
        unsigned ub[13];
#pragma unroll
        for (int k = 0; k < 13; k++) ub[k] = 0u;

        if (u < NUNIT && hh >= 0 && hh < H && ww >= 0 && ww < W) {
            const float sx = __ldg(offx + hh * W + ww);
            const float sy = __ldg(offy + hh * W + ww);

            // ---- x: 4-wide unaligned window ----
            int x0a[3]; float fxa[3], ma[3]; int pmin = W;
#pragma unroll
            for (int dj = 0; dj < 3; dj++) {
                const int wt = ww + 1 - dj;
                float m = (wt >= 0 && wt < W) ? 1.f : 0.f;
                if (ww == 1     && wt == 0    ) m += 1.f;
                if (ww == W - 2 && wt == W - 1) m += 1.f;
                float cx  = fminf(fmaxf((float)wt - sx, 0.f), (float)(W - 1));
                float ix  = cx * ((float)(W - 1) / (float)W);
                float x0f = floorf(ix);
                x0a[dj] = (int)x0f; fxa[dj] = ix - x0f; ma[dj] = m;
                if (m != 0.f) pmin = min(pmin, x0a[dj]);
            }
            const int px = min(max(pmin, 0), W - 4);
            const unsigned parity = (unsigned)(px & 1);
#pragma unroll
            for (int dj = 0; dj < 3; dj++) {
                const int l = min(max(x0a[dj] - px, 0), 2);
                float v[4];
#pragma unroll
                for (int c = 0; c < 4; c++)
                    v[c] = ma[dj] * ((c == l) ? (1.f - fxa[dj])
                                   : ((c == l + 1) ? fxa[dj] : 0.f));
                ub[dj * 2 + 0] = h2pack(v[0], v[1]);
                ub[dj * 2 + 1] = h2pack(v[2], v[3]);
            }

            // ---- y ----
            int y0a[3]; float fya[3], mya[3]; int qmin = H;
#pragma unroll
            for (int di = 0; di < 3; di++) {
                const int ht = hh + 1 - di;
                float m = (ht >= 0 && ht < H) ? 1.f : 0.f;
                if (hh == 1     && ht == 0    ) m += 1.f;
                if (hh == H - 2 && ht == H - 1) m += 1.f;
                float cy  = fminf(fmaxf((float)ht - sy, 0.f), (float)(H - 1));
                float iy  = cy * ((float)(H - 1) / (float)H);
                float y0f = floorf(iy);
                y0a[di] = (int)y0f; fya[di] = iy - y0f; mya[di] = m;
                if (m != 0.f) qmin = min(qmin, y0a[di]);
            }
            const int py = min(qmin, H - 4);
#pragma unroll
            for (int di = 0; di < 3; di++) {
                const int l = min(max(y0a[di] - py, 0), 2);
                float g[4];
#pragma unroll
                for (int r = 0; r < 4; r++)
                    g[r] = mya[di] * ((r == l) ? (1.f - fya[di])
                                    : ((r == l + 1) ? fya[di] : 0.f));
                ub[6 + di] = h2pack(g[0], g[1]);
                ub[9 + di] = h2pack(g[2], g[3]);
            }
            upb[u] = (unsigned)((py * WPAIR + (px >> 1)) * 4) | (parity << 31);
        } else {
            upb[u] = 0u;
        }
        upq[u * 3 + 0] = make_uint4(ub[0], ub[1], ub[2],  ub[3]);
        upq[u * 3 + 1] = make_uint4(ub[4], ub[5], ub[6],  ub[7]);
        upq[u * 3 + 2] = make_uint4(ub[8], ub[9], ub[10], ub[11]);
    }
    __syncthreads();

    // ---------- phase B: 3 waves, NO barriers ----------
    const int cg = tid & 3;
    const int k  = (tid & 31) >> 2;

    for (int wave = 0; wave < NWAVE; wave++) {
        const bool wactive = (wave * 128 + ((tid >> 5) << 3)) < NUNIT;
        if (!wactive) continue;

        const int u = wave * 128 + (tid >> 2);

        const uint4 q0 = upq[u * 3 + 0];
        const uint4 q1 = upq[u * 3 + 1];
        const uint4 q2 = upq[u * 3 + 2];
        const unsigned bw = upb[u];

        const unsigned wxlo[3] = {q0.x, q0.z, q1.x};
        const unsigned wxhi[3] = {q0.y, q0.w, q1.y};
        const unsigned wy01v[3] = {q1.z, q1.w, q2.x};
        const unsigned wy23v[3] = {q2.y, q2.z, q2.w};
        const int base = (int)(bw & 0x7fffffffu) + cg;
        const uint4* __restrict__ imgp = (bw >> 31) ? g_h4o : g_h4e;
        const int ur = u / HALO, uc = u % HALO;

        const __half2 hz = __float2half2_rn(0.f);
        __half2 o01[9], o23[9];
#pragma unroll
        for (int p = 0; p < 9; p++) { o01[p] = hz; o23[p] = hz; }

#pragma unroll
        for (int r = 0; r < 4; r++) {
            const int qb = base + r * (WPAIR * 4);
            const uint4 P0 = __ldg(imgp + qb);
            const uint4 P1 = __ldg(imgp + qb + 4);

            const __half2 C01_0 = u2h(P0.x);
            const __half2 C01_1 = u2h(P0.z);
            const __half2 C01_2 = u2h(P1.x);
            const __half2 C01_3 = u2h(P1.z);
            const __half2 C23_0 = u2h(P0.y);
            const __half2 C23_1 = u2h(P0.w);
            const __half2 C23_2 = u2h(P1.y);
            const __half2 C23_3 = u2h(P1.w);

#pragma unroll
            for (int dj = 0; dj < 3; dj++) {
                const __half2 w0v = __low2half2 (u2h(wxlo[dj]));
                const __half2 w1v = __high2half2(u2h(wxlo[dj]));
                const __half2 w2v = __low2half2 (u2h(wxhi[dj]));
                const __half2 w3v = __high2half2(u2h(wxhi[dj]));

                __half2 t01 = __hmul2(C01_0, w0v);
                __half2 t23 = __hmul2(C23_0, w0v);
                t01 = __hfma2(C01_1, w1v, t01);
                t23 = __hfma2(C23_1, w1v, t23);
                t01 = __hfma2(C01_2, w2v, t01);
                t23 = __hfma2(C23_2, w2v, t23);
                t01 = __hfma2(C01_3, w3v, t01);
                t23 = __hfma2(C23_3, w3v, t23);
#pragma unroll
                for (int di = 0; di < 3; di++) {
                    const unsigned wsel = (r < 2) ? wy01v[di] : wy23v[di];
                    const __half2 g = ((r & 1) == 0) ? __low2half2(u2h(wsel))
                                                     : __high2half2(u2h(wsel));
                    o01[di*3+dj] = __hfma2(t01, g, o01[di*3+dj]);
                    o23[di*3+dj] = __hfma2(t23, g, o23[di*3+dj]);
                }
            }
        }

        // ---- comb stores (store-once; STS.64) ----
#pragma unroll
        for (int di = 0; di < 3; di++) {
            const int row = ur - di;
            const unsigned a1 = __shfl_down_sync(0xffffffffu, h2u(o01[di*3+1]), 4);
            const unsigned b1 = __shfl_down_sync(0xffffffffu, h2u(o23[di*3+1]), 4);
            const unsigned a2 = __shfl_down_sync(0xffffffffu, h2u(o01[di*3+2]), 8);
            const unsigned b2 = __shfl_down_sync(0xffffffffu, h2u(o23[di*3+2]), 8);
            __half2 c01 = o01[di*3+0];
            __half2 c23 = o23[di*3+0];
            if (k <= 6) { c01 = __hadd2(c01, u2h(a1)); c23 = __hadd2(c23, u2h(b1)); }
            if (k <= 5) { c01 = __hadd2(c01, u2h(a2)); c23 = __hadd2(c23, u2h(b2)); }
            if ((unsigned)row < (unsigned)TILE && (unsigned)uc < (unsigned)TILE) {
                comb[di][(row * TILE + uc) * 4 + cg] = make_uint2(h2u(c01), h2u(c23));
            }
        }

        // ---- leftovers (k==0 lanes; store-once, proven distinct) ----
#pragma unroll
        for (int di = 0; di < 3; di++) {
            const int row = ur - di;
            const unsigned la = __shfl_down_sync(0xffffffffu, h2u(o01[di*3+2]), 4);
            const unsigned lb = __shfl_down_sync(0xffffffffu, h2u(o23[di*3+2]), 4);
            if (k == 0) {
                if ((unsigned)row < (unsigned)TILE &&
                    (unsigned)(uc - 1) < (unsigned)TILE) {
                    lft[(row * TILE + (uc - 1)) * 4 + cg] =
                        make_uint2(h2u(__hadd2(o01[di*3+1], u2h(la))),
                                   h2u(__hadd2(o23[di*3+1], u2h(lb))));
                }
                if ((unsigned)row < (unsigned)TILE &&
                    (unsigned)(uc - 2) < (unsigned)TILE) {
                    lft[(row * TILE + (uc - 2)) * 4 + cg] =
                        make_uint2(h2u(o01[di*3+2]), h2u(o23[di*3+2]));
                }
            }
        }
    }
    __syncthreads();

    // ---------- writeback ----------
    const float inv9 = 1.0f / 9.0f;
#pragma unroll
    for (int pass = 0; pass < 2; pass++) {
        const int a = pass * THREADS + tid;
        const int cell = a >> 2;
        const int acg  = a & 3;
        const int gidx = (h0 + (cell >> 4)) * W + (w0 + (cell & 15));

        const uint2 L = lft[a];
        float2 s01 = __half22float2(u2h(L.x));
        float2 s23 = __half22float2(u2h(L.y));
#pragma unroll
        for (int di = 0; di < 3; di++) {
            const uint2 Cc = comb[di][a];
            const float2 c0 = __half22float2(u2h(Cc.x));
            const float2 c2 = __half22float2(u2h(Cc.y));
            s01.x += c0.x; s01.y += c0.y;
            s23.x += c2.x; s23.y += c2.y;
        }
        out[(4*acg + 0) * HW + gidx] = s01.x * inv9;
        out[(4*acg + 1) * HW + gidx] = s01.y * inv9;
        out[(4*acg + 2) * HW + gidx] = s23.x * inv9;
        out[(4*acg + 3) * HW + gidx] = s23.y * inv9;
    }
}

extern "C" void kernel_launch(void* const* d_in, const int* in_sizes, int n_in,
                              void* d_out, int out_size)
{
    const float* img  = (const float*)d_in[0];
    const float* offx = (const float*)d_in[1];
    const float* offy = (const float*)d_in[2];
    float* out = (float*)d_out;

    transpose_kernel<<<1920, 256>>>(img);

    dim3 grid(W / TILE, H / TILE);
    recon_scatter<<<grid, THREADS>>>(offx, offy, out);
}